// round 14
// baseline (speedup 1.0000x reference)
#include <cuda_runtime.h>
#include <cuda_fp16.h>
#include <cstdint>

#define T_TOK 32768
#define D_DIM 1024
#define H_DIM 2048
#define O_DIM 1024
#define NE 8
#define TOPK 4
#define NPAIR (T_TOK * TOPK)            // 131072
#define MAXROWS (NPAIR + NE * 128)      // 132096
#define MAXTILES (MAXROWS / 128)        // 1032

#define KT 64                            // k-tile
#define LDAH 72                          // halves per smem row (64 + 8 pad)
#define A_ST (128 * LDAH)                // 9216 halves per tile
#define STAGE_H (2 * A_ST)               // 18432 halves per stage
#define GEMM_SMEM (2 * STAGE_H * 2)      // 73728 bytes (>= 128*132*4 epilogue)

// ---- scratch (__device__ globals; allocation-free rule) ----
__device__ __half g_xnh[(size_t)T_TOK * D_DIM];          // 64 MB
__device__ __half g_hh[(size_t)MAXROWS * H_DIM];         // 516 MB
__device__ __half g_yph[(size_t)NPAIR * O_DIM];          // 256 MB (half partials)
__device__ __half g_w1t[(size_t)NE * H_DIM * D_DIM];     // [E][H][D]
__device__ __half g_w2t[(size_t)NE * O_DIM * H_DIM];     // [E][O][H]
__device__ int    g_sel[NPAIR];
__device__ float  g_gval[NPAIR];
__device__ int    g_cnt[NE];
__device__ int    g_fill[NE];
__device__ int    g_off[NE];
__device__ int    g_tok[MAXROWS];
__device__ int    g_pair[MAXROWS];
__device__ float  g_gateS[MAXROWS];
__device__ int    g_texp[MAXTILES];

__device__ __forceinline__ float gelu_exact(float v) { return v * normcdff(v); }

__device__ __forceinline__ void cp16(void* dst, const void* src) {
    unsigned d = (unsigned)__cvta_generic_to_shared(dst);
    asm volatile("cp.async.cg.shared.global [%0], [%1], 16;\n" ::"r"(d), "l"(src));
}

__device__ __forceinline__ void ldm_x4(uint32_t* r, uint32_t saddr) {
    asm volatile("ldmatrix.sync.aligned.m8n8.x4.shared.b16 {%0,%1,%2,%3}, [%4];"
                 : "=r"(r[0]), "=r"(r[1]), "=r"(r[2]), "=r"(r[3]) : "r"(saddr));
}

__device__ __forceinline__ void mma16n8k16(float* d, const uint32_t* a, const uint32_t* b) {
    asm volatile(
        "mma.sync.aligned.m16n8k16.row.col.f32.f16.f16.f32 "
        "{%0,%1,%2,%3}, {%4,%5,%6,%7}, {%8,%9}, {%0,%1,%2,%3};\n"
        : "+f"(d[0]), "+f"(d[1]), "+f"(d[2]), "+f"(d[3])
        : "r"(a[0]), "r"(a[1]), "r"(a[2]), "r"(a[3]), "r"(b[0]), "r"(b[1]));
}

// ---------------------------------------------------------------------------
// Kernel 0: fp32 [R][C] -> half transposed [C][R], per expert (blockIdx.z)
// ---------------------------------------------------------------------------
__global__ void transpose_h_kernel(const float* __restrict__ src,
                                   __half* __restrict__ dst, int R, int C) {
    __shared__ float tile[32][33];
    const float* s = src + (size_t)blockIdx.z * R * C;
    __half* d = dst + (size_t)blockIdx.z * R * C;
    int c0 = blockIdx.x * 32, r0 = blockIdx.y * 32;
    int tx = threadIdx.x, ty = threadIdx.y;  // (32, 8)
#pragma unroll
    for (int j = 0; j < 4; j++)
        tile[ty + j * 8][tx] = s[(size_t)(r0 + ty + j * 8) * C + c0 + tx];
    __syncthreads();
#pragma unroll
    for (int j = 0; j < 4; j++)
        d[(size_t)(c0 + ty + j * 8) * R + r0 + tx] =
            __float2half_rn(tile[tx][ty + j * 8]);
}

// ---------------------------------------------------------------------------
// Kernel 1: warp-per-token LayerNorm + router + top-4 softmax + fused count.
// ---------------------------------------------------------------------------
__global__ __launch_bounds__(256) void ln_router_kernel(
    const float* __restrict__ x, const float* __restrict__ gamma,
    const float* __restrict__ beta, const float* __restrict__ rw,
    const float* __restrict__ rb) {
    __shared__ int hist[NE];
    const int tid = threadIdx.x;
    const int warp = tid >> 5, lane = tid & 31;
    if (tid < NE) hist[tid] = 0;
    __syncthreads();

    const int t = blockIdx.x * 8 + warp;
    const float* xr = x + (size_t)t * D_DIM;

    float v[32];
    float s = 0.f, ss = 0.f;
#pragma unroll
    for (int i = 0; i < 32; i++) {
        float val = xr[lane + (i << 5)];
        v[i] = val; s += val; ss += val * val;
    }
#pragma unroll
    for (int o = 16; o > 0; o >>= 1) {
        s += __shfl_xor_sync(0xffffffffu, s, o);
        ss += __shfl_xor_sync(0xffffffffu, ss, o);
    }
    const float mu = s * (1.f / D_DIM);
    const float var = ss * (1.f / D_DIM) - mu * mu;
    const float rstd = rsqrtf(var + 1e-5f);

    float lg[NE];
#pragma unroll
    for (int e = 0; e < NE; e++) lg[e] = 0.f;
    __half* xnout = g_xnh + (size_t)t * D_DIM;
#pragma unroll
    for (int i = 0; i < 32; i++) {
        int idx = lane + (i << 5);
        float xn = (v[i] - mu) * rstd * gamma[idx] + beta[idx];
        xnout[idx] = __float2half_rn(xn);
        const float* w = rw + (size_t)idx * NE;
#pragma unroll
        for (int e = 0; e < NE; e++) lg[e] += xn * w[e];
    }
#pragma unroll
    for (int e = 0; e < NE; e++)
#pragma unroll
        for (int o = 16; o > 0; o >>= 1)
            lg[e] += __shfl_xor_sync(0xffffffffu, lg[e], o);

    if (lane == 0) {
        float logit[NE];
#pragma unroll
        for (int e = 0; e < NE; e++) logit[e] = lg[e] + rb[e];
        int sel[TOPK]; float mv[TOPK]; bool used[NE];
#pragma unroll
        for (int e = 0; e < NE; e++) used[e] = false;
#pragma unroll
        for (int k = 0; k < TOPK; k++) {
            int bi = 0; float bv = -3.4e38f;
#pragma unroll
            for (int e = 0; e < NE; e++)
                if (!used[e] && logit[e] > bv) { bv = logit[e]; bi = e; }
            used[bi] = true; sel[k] = bi; mv[k] = bv;
        }
        const float m = mv[0];
        float den = 0.f, ex[TOPK];
#pragma unroll
        for (int k = 0; k < TOPK; k++) { ex[k] = expf(mv[k] - m); den += ex[k]; }
#pragma unroll
        for (int k = 0; k < TOPK; k++) {
            g_sel[t * TOPK + k]  = sel[k];
            g_gval[t * TOPK + k] = ex[k] / den;
            atomicAdd(&hist[sel[k]], 1);
        }
    }
    __syncthreads();
    if (tid < NE) atomicAdd(&g_cnt[tid], hist[tid]);
}

// ---------------------------------------------------------------------------
// Kernel 3: offsets (1 block, serial prefix + parallel texp fill)
// ---------------------------------------------------------------------------
__global__ void offsets_kernel() {
    __shared__ int tstart[NE + 1];
    const int tid = threadIdx.x;  // 256
    if (tid == 0) {
        int off = 0, tile = 0;
        for (int e = 0; e < NE; e++) {
            g_off[e] = off;
            tstart[e] = tile;
            int tiles_e = (g_cnt[e] + 127) >> 7;
            tile += tiles_e;
            off += tiles_e << 7;
        }
        tstart[NE] = tile;
    }
    __syncthreads();
    for (int i = tid; i < MAXTILES; i += 256) {
        int e = -1;
#pragma unroll
        for (int q = 0; q < NE; q++)
            if (i >= tstart[q] && i < tstart[q + 1]) e = q;
        g_texp[i] = e;
    }
}

// ---------------------------------------------------------------------------
// Kernel 4: scatter
// ---------------------------------------------------------------------------
__global__ void scatter_kernel() {
    __shared__ int lcnt[NE], lbase[NE];
    const int tid = threadIdx.x;  // 128
    const int t = blockIdx.x * 128 + tid;
    if (tid < NE) lcnt[tid] = 0;
    __syncthreads();
    int myidx[TOPK], mye[TOPK]; float myg[TOPK];
#pragma unroll
    for (int k = 0; k < TOPK; k++) {
        int e = g_sel[t * TOPK + k];
        mye[k] = e;
        myg[k] = g_gval[t * TOPK + k];
        myidx[k] = atomicAdd(&lcnt[e], 1);
    }
    __syncthreads();
    if (tid < NE) lbase[tid] = atomicAdd(&g_fill[tid], lcnt[tid]);
    __syncthreads();
#pragma unroll
    for (int k = 0; k < TOPK; k++) {
        int pos = g_off[mye[k]] + lbase[mye[k]] + myidx[k];
        g_tok[pos]   = t;
        g_pair[pos]  = t * TOPK + k;
        g_gateS[pos] = myg[k];
    }
}

// ---------------------------------------------------------------------------
// Kernel 5: fp16 GEMM, 128x128 CTA tile, K-tile 64, 4 warps (2x2), warp 64x64,
// mma.m16n8k16 + ldmatrix, register double-buffered fragments, 2-stage
// cp.async, 2 CTAs/SM.  Single-phase epilogue (128x132 fp32 in smem).
// ---------------------------------------------------------------------------
__global__ __launch_bounds__(128, 2) void moe_gemm_h(
    const __half* __restrict__ A, const __half* __restrict__ B,
    const float* __restrict__ bias, __half* __restrict__ Out,
    int K, int N, int isGemm1) {
    extern __shared__ __half smh[];
    __shared__ int   stok[128];
    __shared__ float sgate[128];

    const int tid = threadIdx.x;     // 128
    const int warp = tid >> 5;
    const int lane = tid & 31;
    const int tig = lane & 3;
    const int wm = warp >> 1;        // 0..1
    const int wn = warp & 1;         // 0..1
    const int te = g_texp[blockIdx.y];
    if (te < 0) return;
    const int r0 = blockIdx.y * 128;
    const int n0 = blockIdx.x * 128;
    const __half* Bp = B + (size_t)te * K * N;   // [N][K] n-major
    const float* biasp = bias + (size_t)te * N;

    if (isGemm1) {
        stok[tid] = g_tok[r0 + tid];
        __syncthreads();
    }

    const int srow = tid >> 3, sc8 = (tid & 7) * 8;
    const __half* asrc[8];
#pragma unroll
    for (int j = 0; j < 8; j++) {
        int r = srow + j * 16;
        if (isGemm1) {
            int tk = stok[r]; if (tk < 0) tk = 0;
            asrc[j] = g_xnh + (size_t)tk * D_DIM + sc8;
        } else {
            asrc[j] = A + (size_t)(r0 + r) * K + sc8;
        }
    }
    const __half* bsrc[8];
#pragma unroll
    for (int j = 0; j < 8; j++) {
        int r = srow + j * 16;
        bsrc[j] = Bp + (size_t)(n0 + r) * K + sc8;
    }

    float acc[4][8][4];
#pragma unroll
    for (int mi = 0; mi < 4; mi++)
#pragma unroll
        for (int ni = 0; ni < 8; ni++)
#pragma unroll
            for (int q = 0; q < 4; q++) acc[mi][ni][q] = 0.f;

    const uint32_t sA0 = (uint32_t)__cvta_generic_to_shared(smh);
    const int a_lr = (lane & 7) + ((lane >> 3) & 1) * 8;
    const int a_lc = ((lane >> 4) & 1) * 8;
    const int b_lr = (lane & 7) + ((lane >> 4) & 1) * 8;
    const int b_lc = ((lane >> 3) & 1) * 8;

    const int ktiles = K / KT;

#define STAGE(s, kt)                                                   \
    do {                                                               \
        __half* sa_ = smh + (s) * STAGE_H;                             \
        __half* sb_ = sa_ + A_ST;                                      \
        _Pragma("unroll")                                              \
        for (int j = 0; j < 8; j++) {                                  \
            int r = srow + j * 16;                                     \
            cp16(sa_ + r * LDAH + sc8, asrc[j] + (kt) * KT);           \
            cp16(sb_ + r * LDAH + sc8, bsrc[j] + (kt) * KT);           \
        }                                                              \
        asm volatile("cp.async.commit_group;\n");                      \
    } while (0)

    uint32_t afr[2][4][4];
    uint32_t bfr[2][8][2];

#define LOADFRAG(buf, ks_)                                                     \
    do {                                                                       \
        _Pragma("unroll")                                                      \
        for (int mi = 0; mi < 4; mi++)                                         \
            ldm_x4(afr[buf][mi],                                               \
                   sAu + (uint32_t)(((wm * 64 + mi * 16 + a_lr) * LDAH +       \
                                     (ks_) * 16 + a_lc) * 2));                 \
        _Pragma("unroll")                                                      \
        for (int np = 0; np < 4; np++) {                                       \
            uint32_t tmp[4];                                                   \
            ldm_x4(tmp,                                                        \
                   sBu + (uint32_t)(((wn * 64 + np * 16 + b_lr) * LDAH +       \
                                     (ks_) * 16 + b_lc) * 2));                 \
            bfr[buf][2 * np][0] = tmp[0]; bfr[buf][2 * np][1] = tmp[1];        \
            bfr[buf][2 * np + 1][0] = tmp[2]; bfr[buf][2 * np + 1][1] = tmp[3];\
        }                                                                      \
    } while (0)

    STAGE(0, 0);
    for (int kt = 0; kt < ktiles; kt++) {
        const int s = kt & 1;
        if (kt + 1 < ktiles) {
            STAGE(s ^ 1, kt + 1);
            asm volatile("cp.async.wait_group 1;\n");
        } else {
            asm volatile("cp.async.wait_group 0;\n");
        }
        __syncthreads();

        const uint32_t sAu = sA0 + (uint32_t)(s * STAGE_H) * 2u;
        const uint32_t sBu = sAu + (uint32_t)A_ST * 2u;

        LOADFRAG(0, 0);
#pragma unroll
        for (int ks = 0; ks < 4; ks++) {
            const int cur = ks & 1;
            if (ks + 1 < 4) LOADFRAG(cur ^ 1, ks + 1);
#pragma unroll
            for (int mi = 0; mi < 4; mi++)
#pragma unroll
                for (int ni = 0; ni < 8; ni++)
                    mma16n8k16(acc[mi][ni], afr[cur][mi], bfr[cur][ni]);
        }
        __syncthreads();
    }
#undef STAGE
#undef LOADFRAG

    if (!isGemm1) {
        stok[tid]  = g_pair[r0 + tid];
        sgate[tid] = g_gateS[r0 + tid];
    }
    __syncthreads();   // mainloop smem reads done before epilogue overwrite

    // single-phase epilogue: full 128x132 fp32 tile in smem
    float* sC = (float*)smh;
    const int gid = lane >> 2;
#pragma unroll
    for (int mi = 0; mi < 4; mi++)
#pragma unroll
        for (int ni = 0; ni < 8; ni++) {
            int rr = wm * 64 + mi * 16 + gid;
            int cc = wn * 64 + ni * 8 + 2 * tig;
            sC[rr * 132 + cc]           = acc[mi][ni][0];
            sC[rr * 132 + cc + 1]       = acc[mi][ni][1];
            sC[(rr + 8) * 132 + cc]     = acc[mi][ni][2];
            sC[(rr + 8) * 132 + cc + 1] = acc[mi][ni][3];
        }
    __syncthreads();
#pragma unroll
    for (int j = 0; j < 32; j++) {
        int f = tid + j * 128;               // 4096 float4s = 128x128
        int r = f >> 5, c = (f & 31) << 2;
        int gn = n0 + c;
        float4 cv = *(float4*)(sC + r * 132 + c);
        float4 bv = *(const float4*)(biasp + gn);
        if (isGemm1) {
            __half2 h0 = __floats2half2_rn(gelu_exact(cv.x + bv.x),
                                           gelu_exact(cv.y + bv.y));
            __half2 h1 = __floats2half2_rn(gelu_exact(cv.z + bv.z),
                                           gelu_exact(cv.w + bv.w));
            uint2 pk;
            pk.x = *(uint32_t*)&h0;
            pk.y = *(uint32_t*)&h1;
            *(uint2*)(Out + (size_t)(r0 + r) * N + gn) = pk;
        } else {
            int pair = stok[r];
            if (pair >= 0) {
                float g = sgate[r];
                __half2 h0 = __floats2half2_rn((cv.x + bv.x) * g,
                                               (cv.y + bv.y) * g);
                __half2 h1 = __floats2half2_rn((cv.z + bv.z) * g,
                                               (cv.w + bv.w) * g);
                uint2 pk;
                pk.x = *(uint32_t*)&h0;
                pk.y = *(uint32_t*)&h1;
                *(uint2*)(Out + (size_t)pair * N + gn) = pk;
            }
        }
    }
}

// ---------------------------------------------------------------------------
// Kernel 6: combine 4 half pair contributions per token (fixed order, fp32 acc)
// ---------------------------------------------------------------------------
__global__ void combine_kernel(float* __restrict__ y) {
    const int i = blockIdx.x * 256 + threadIdx.x;  // over T*O/4 groups
    const int t = i >> 8;                          // O/4 = 256 groups per token
    const int c = i & 255;
    const uint2* yp = (const uint2*)g_yph;         // 4 halves per uint2
    size_t base = (size_t)t * TOPK * 256 + c;
    float4 s = make_float4(0.f, 0.f, 0.f, 0.f);
#pragma unroll
    for (int k = 0; k < TOPK; k++) {
        uint2 pk = yp[base + (size_t)k * 256];
        __half2 h0 = *(__half2*)&pk.x;
        __half2 h1 = *(__half2*)&pk.y;
        float2 f0 = __half22float2(h0);
        float2 f1 = __half22float2(h1);
        s.x += f0.x; s.y += f0.y; s.z += f1.x; s.w += f1.y;
    }
    ((float4*)y)[i] = s;
}

// ---------------------------------------------------------------------------
extern "C" void kernel_launch(void* const* d_in, const int* in_sizes, int n_in,
                              void* d_out, int out_size) {
    const float* x     = (const float*)d_in[0];
    const float* gamma = (const float*)d_in[1];
    const float* beta  = (const float*)d_in[2];
    const float* rw    = (const float*)d_in[3];
    const float* rb    = (const float*)d_in[4];
    const float* w1    = (const float*)d_in[5];
    const float* b1    = (const float*)d_in[6];
    const float* w2    = (const float*)d_in[7];
    const float* b2    = (const float*)d_in[8];
    float* y = (float*)d_out;

    __half *xnh_p = nullptr, *hh_p = nullptr, *yph_p = nullptr;
    __half *w1t_p = nullptr, *w2t_p = nullptr;
    int *cnt_p = nullptr, *fill_p = nullptr, *tok_p = nullptr, *pair_p = nullptr;
    cudaGetSymbolAddress((void**)&xnh_p, g_xnh);
    cudaGetSymbolAddress((void**)&hh_p, g_hh);
    cudaGetSymbolAddress((void**)&yph_p, g_yph);
    cudaGetSymbolAddress((void**)&w1t_p, g_w1t);
    cudaGetSymbolAddress((void**)&w2t_p, g_w2t);
    cudaGetSymbolAddress((void**)&cnt_p, g_cnt);
    cudaGetSymbolAddress((void**)&fill_p, g_fill);
    cudaGetSymbolAddress((void**)&tok_p, g_tok);
    cudaGetSymbolAddress((void**)&pair_p, g_pair);

    cudaFuncSetAttribute(moe_gemm_h,
                         cudaFuncAttributeMaxDynamicSharedMemorySize, GEMM_SMEM);

    cudaMemsetAsync(cnt_p, 0, NE * sizeof(int));
    cudaMemsetAsync(fill_p, 0, NE * sizeof(int));
    cudaMemsetAsync(tok_p, 0xFF, MAXROWS * sizeof(int));
    cudaMemsetAsync(pair_p, 0xFF, MAXROWS * sizeof(int));

    dim3 tb(32, 8);
    transpose_h_kernel<<<dim3(H_DIM / 32, D_DIM / 32, NE), tb>>>(w1, w1t_p, D_DIM, H_DIM);
    transpose_h_kernel<<<dim3(O_DIM / 32, H_DIM / 32, NE), tb>>>(w2, w2t_p, H_DIM, O_DIM);

    ln_router_kernel<<<T_TOK / 8, 256>>>(x, gamma, beta, rw, rb);
    offsets_kernel<<<1, 256>>>();
    scatter_kernel<<<T_TOK / 128, 128>>>();

    dim3 g1(H_DIM / 128, MAXTILES);
    dim3 g2(O_DIM / 128, MAXTILES);
    moe_gemm_h<<<g1, 128, GEMM_SMEM>>>(xnh_p, w1t_p, b1, hh_p, D_DIM, H_DIM, 1);
    moe_gemm_h<<<g2, 128, GEMM_SMEM>>>(hh_p, w2t_p, b2, yph_p, H_DIM, O_DIM, 0);

    combine_kernel<<<(T_TOK * O_DIM / 4) / 256, 256>>>(y);
}

// round 15
// speedup vs baseline: 1.1208x; 1.1208x over previous
#include <cuda_runtime.h>
#include <cuda_fp16.h>
#include <cstdint>

#define T_TOK 32768
#define D_DIM 1024
#define H_DIM 2048
#define O_DIM 1024
#define NE 8
#define TOPK 4
#define NPAIR (T_TOK * TOPK)            // 131072
#define MAXROWS (NPAIR + NE * 128)      // 132096
#define MAXTILES (MAXROWS / 128)        // 1032

#define KT 64                            // k-tile
#define LDAH 72                          // halves per smem row (64 + 8 pad)
#define A_ST (128 * LDAH)                // 9216 halves per tile
#define STAGE_H (2 * A_ST)               // 18432 halves per stage
#define GEMM_SMEM (2 * STAGE_H * 2)      // 73728 bytes

// ---- scratch (__device__ globals; allocation-free rule) ----
__device__ __half g_xnh[(size_t)T_TOK * D_DIM];          // 64 MB
__device__ __half g_hh[(size_t)MAXROWS * H_DIM];         // 516 MB
__device__ __half g_yph[(size_t)NPAIR * O_DIM];          // 256 MB (half partials)
__device__ __half g_w1t[(size_t)NE * H_DIM * D_DIM];     // [E][H][D]
__device__ __half g_w2t[(size_t)NE * O_DIM * H_DIM];     // [E][O][H]
__device__ int    g_sel[NPAIR];
__device__ float  g_gval[NPAIR];
__device__ int    g_cnt[NE];
__device__ int    g_fill[NE];
__device__ int    g_off[NE];
__device__ int    g_tok[MAXROWS];
__device__ int    g_pair[MAXROWS];
__device__ float  g_gateS[MAXROWS];
__device__ int    g_texp[MAXTILES];

__device__ __forceinline__ float gelu_exact(float v) { return v * normcdff(v); }

__device__ __forceinline__ void cp16(void* dst, const void* src) {
    unsigned d = (unsigned)__cvta_generic_to_shared(dst);
    asm volatile("cp.async.cg.shared.global [%0], [%1], 16;\n" ::"r"(d), "l"(src));
}

__device__ __forceinline__ void ldm_x4(uint32_t* r, uint32_t saddr) {
    asm volatile("ldmatrix.sync.aligned.m8n8.x4.shared.b16 {%0,%1,%2,%3}, [%4];"
                 : "=r"(r[0]), "=r"(r[1]), "=r"(r[2]), "=r"(r[3]) : "r"(saddr));
}

__device__ __forceinline__ void mma16n8k16(float* d, const uint32_t* a, const uint32_t* b) {
    asm volatile(
        "mma.sync.aligned.m16n8k16.row.col.f32.f16.f16.f32 "
        "{%0,%1,%2,%3}, {%4,%5,%6,%7}, {%8,%9}, {%0,%1,%2,%3};\n"
        : "+f"(d[0]), "+f"(d[1]), "+f"(d[2]), "+f"(d[3])
        : "r"(a[0]), "r"(a[1]), "r"(a[2]), "r"(a[3]), "r"(b[0]), "r"(b[1]));
}

// ---------------------------------------------------------------------------
// Kernel 0: fp32 [R][C] -> half transposed [C][R], per expert (blockIdx.z)
// ---------------------------------------------------------------------------
__global__ void transpose_h_kernel(const float* __restrict__ src,
                                   __half* __restrict__ dst, int R, int C) {
    __shared__ float tile[32][33];
    const float* s = src + (size_t)blockIdx.z * R * C;
    __half* d = dst + (size_t)blockIdx.z * R * C;
    int c0 = blockIdx.x * 32, r0 = blockIdx.y * 32;
    int tx = threadIdx.x, ty = threadIdx.y;  // (32, 8)
#pragma unroll
    for (int j = 0; j < 4; j++)
        tile[ty + j * 8][tx] = s[(size_t)(r0 + ty + j * 8) * C + c0 + tx];
    __syncthreads();
#pragma unroll
    for (int j = 0; j < 4; j++)
        d[(size_t)(c0 + ty + j * 8) * R + r0 + tx] =
            __float2half_rn(tile[tx][ty + j * 8]);
}

// ---------------------------------------------------------------------------
// Kernel 1: warp-per-token LayerNorm + router + top-4 softmax + fused count.
// ---------------------------------------------------------------------------
__global__ __launch_bounds__(256) void ln_router_kernel(
    const float* __restrict__ x, const float* __restrict__ gamma,
    const float* __restrict__ beta, const float* __restrict__ rw,
    const float* __restrict__ rb) {
    __shared__ int hist[NE];
    const int tid = threadIdx.x;
    const int warp = tid >> 5, lane = tid & 31;
    if (tid < NE) hist[tid] = 0;
    __syncthreads();

    const int t = blockIdx.x * 8 + warp;
    const float* xr = x + (size_t)t * D_DIM;

    float v[32];
    float s = 0.f, ss = 0.f;
#pragma unroll
    for (int i = 0; i < 32; i++) {
        float val = xr[lane + (i << 5)];
        v[i] = val; s += val; ss += val * val;
    }
#pragma unroll
    for (int o = 16; o > 0; o >>= 1) {
        s += __shfl_xor_sync(0xffffffffu, s, o);
        ss += __shfl_xor_sync(0xffffffffu, ss, o);
    }
    const float mu = s * (1.f / D_DIM);
    const float var = ss * (1.f / D_DIM) - mu * mu;
    const float rstd = rsqrtf(var + 1e-5f);

    float lg[NE];
#pragma unroll
    for (int e = 0; e < NE; e++) lg[e] = 0.f;
    __half* xnout = g_xnh + (size_t)t * D_DIM;
#pragma unroll
    for (int i = 0; i < 32; i++) {
        int idx = lane + (i << 5);
        float xn = (v[i] - mu) * rstd * gamma[idx] + beta[idx];
        xnout[idx] = __float2half_rn(xn);
        const float* w = rw + (size_t)idx * NE;
#pragma unroll
        for (int e = 0; e < NE; e++) lg[e] += xn * w[e];
    }
#pragma unroll
    for (int e = 0; e < NE; e++)
#pragma unroll
        for (int o = 16; o > 0; o >>= 1)
            lg[e] += __shfl_xor_sync(0xffffffffu, lg[e], o);

    if (lane == 0) {
        float logit[NE];
#pragma unroll
        for (int e = 0; e < NE; e++) logit[e] = lg[e] + rb[e];
        int sel[TOPK]; float mv[TOPK]; bool used[NE];
#pragma unroll
        for (int e = 0; e < NE; e++) used[e] = false;
#pragma unroll
        for (int k = 0; k < TOPK; k++) {
            int bi = 0; float bv = -3.4e38f;
#pragma unroll
            for (int e = 0; e < NE; e++)
                if (!used[e] && logit[e] > bv) { bv = logit[e]; bi = e; }
            used[bi] = true; sel[k] = bi; mv[k] = bv;
        }
        const float m = mv[0];
        float den = 0.f, ex[TOPK];
#pragma unroll
        for (int k = 0; k < TOPK; k++) { ex[k] = expf(mv[k] - m); den += ex[k]; }
#pragma unroll
        for (int k = 0; k < TOPK; k++) {
            g_sel[t * TOPK + k]  = sel[k];
            g_gval[t * TOPK + k] = ex[k] / den;
            atomicAdd(&hist[sel[k]], 1);
        }
    }
    __syncthreads();
    if (tid < NE) atomicAdd(&g_cnt[tid], hist[tid]);
}

// ---------------------------------------------------------------------------
// Kernel 3: offsets (1 block, serial prefix + parallel texp fill)
// ---------------------------------------------------------------------------
__global__ void offsets_kernel() {
    __shared__ int tstart[NE + 1];
    const int tid = threadIdx.x;  // 256
    if (tid == 0) {
        int off = 0, tile = 0;
        for (int e = 0; e < NE; e++) {
            g_off[e] = off;
            tstart[e] = tile;
            int tiles_e = (g_cnt[e] + 127) >> 7;
            tile += tiles_e;
            off += tiles_e << 7;
        }
        tstart[NE] = tile;
    }
    __syncthreads();
    for (int i = tid; i < MAXTILES; i += 256) {
        int e = -1;
#pragma unroll
        for (int q = 0; q < NE; q++)
            if (i >= tstart[q] && i < tstart[q + 1]) e = q;
        g_texp[i] = e;
    }
}

// ---------------------------------------------------------------------------
// Kernel 4: scatter
// ---------------------------------------------------------------------------
__global__ void scatter_kernel() {
    __shared__ int lcnt[NE], lbase[NE];
    const int tid = threadIdx.x;  // 128
    const int t = blockIdx.x * 128 + tid;
    if (tid < NE) lcnt[tid] = 0;
    __syncthreads();
    int myidx[TOPK], mye[TOPK]; float myg[TOPK];
#pragma unroll
    for (int k = 0; k < TOPK; k++) {
        int e = g_sel[t * TOPK + k];
        mye[k] = e;
        myg[k] = g_gval[t * TOPK + k];
        myidx[k] = atomicAdd(&lcnt[e], 1);
    }
    __syncthreads();
    if (tid < NE) lbase[tid] = atomicAdd(&g_fill[tid], lcnt[tid]);
    __syncthreads();
#pragma unroll
    for (int k = 0; k < TOPK; k++) {
        int pos = g_off[mye[k]] + lbase[mye[k]] + myidx[k];
        g_tok[pos]   = t;
        g_pair[pos]  = t * TOPK + k;
        g_gateS[pos] = myg[k];
    }
}

// ---------------------------------------------------------------------------
// Kernel 5: fp16 GEMM, 128x128 CTA tile, K-tile 64, 4 warps (2x2), warp 64x64,
// mma.m16n8k16 + ldmatrix with register double-buffered fragments,
// 2-stage cp.async (stores before wait), 2 CTAs/SM.  [R12 exact, frozen]
// ---------------------------------------------------------------------------
__global__ __launch_bounds__(128, 2) void moe_gemm_h(
    const __half* __restrict__ A, const __half* __restrict__ B,
    const float* __restrict__ bias, __half* __restrict__ Out,
    int K, int N, int isGemm1) {
    extern __shared__ __half smh[];
    __shared__ int   stok[128];
    __shared__ float sgate[128];

    const int tid = threadIdx.x;     // 128
    const int warp = tid >> 5;
    const int lane = tid & 31;
    const int tig = lane & 3;
    const int wm = warp >> 1;        // 0..1
    const int wn = warp & 1;         // 0..1
    const int te = g_texp[blockIdx.y];
    if (te < 0) return;
    const int r0 = blockIdx.y * 128;
    const int n0 = blockIdx.x * 128;
    const __half* Bp = B + (size_t)te * K * N;   // [N][K] n-major
    const float* biasp = bias + (size_t)te * N;

    if (isGemm1) {
        stok[tid] = g_tok[r0 + tid];
        __syncthreads();
    }

    const int srow = tid >> 3, sc8 = (tid & 7) * 8;
    const __half* asrc[8];
#pragma unroll
    for (int j = 0; j < 8; j++) {
        int r = srow + j * 16;
        if (isGemm1) {
            int tk = stok[r]; if (tk < 0) tk = 0;
            asrc[j] = g_xnh + (size_t)tk * D_DIM + sc8;
        } else {
            asrc[j] = A + (size_t)(r0 + r) * K + sc8;
        }
    }
    const __half* bsrc[8];
#pragma unroll
    for (int j = 0; j < 8; j++) {
        int r = srow + j * 16;
        bsrc[j] = Bp + (size_t)(n0 + r) * K + sc8;
    }

    float acc[4][8][4];
#pragma unroll
    for (int mi = 0; mi < 4; mi++)
#pragma unroll
        for (int ni = 0; ni < 8; ni++)
#pragma unroll
            for (int q = 0; q < 4; q++) acc[mi][ni][q] = 0.f;

    const uint32_t sA0 = (uint32_t)__cvta_generic_to_shared(smh);
    const int a_lr = (lane & 7) + ((lane >> 3) & 1) * 8;
    const int a_lc = ((lane >> 4) & 1) * 8;
    const int b_lr = (lane & 7) + ((lane >> 4) & 1) * 8;
    const int b_lc = ((lane >> 3) & 1) * 8;

    const int ktiles = K / KT;

#define STAGE(s, kt)                                                   \
    do {                                                               \
        __half* sa_ = smh + (s) * STAGE_H;                             \
        __half* sb_ = sa_ + A_ST;                                      \
        _Pragma("unroll")                                              \
        for (int j = 0; j < 8; j++) {                                  \
            int r = srow + j * 16;                                     \
            cp16(sa_ + r * LDAH + sc8, asrc[j] + (kt) * KT);           \
            cp16(sb_ + r * LDAH + sc8, bsrc[j] + (kt) * KT);           \
        }                                                              \
        asm volatile("cp.async.commit_group;\n");                      \
    } while (0)

    uint32_t afr[2][4][4];
    uint32_t bfr[2][8][2];

#define LOADFRAG(buf, ks_)                                                     \
    do {                                                                       \
        _Pragma("unroll")                                                      \
        for (int mi = 0; mi < 4; mi++)                                         \
            ldm_x4(afr[buf][mi],                                               \
                   sAu + (uint32_t)(((wm * 64 + mi * 16 + a_lr) * LDAH +       \
                                     (ks_) * 16 + a_lc) * 2));                 \
        _Pragma("unroll")                                                      \
        for (int np = 0; np < 4; np++) {                                       \
            uint32_t tmp[4];                                                   \
            ldm_x4(tmp,                                                        \
                   sBu + (uint32_t)(((wn * 64 + np * 16 + b_lr) * LDAH +       \
                                     (ks_) * 16 + b_lc) * 2));                 \
            bfr[buf][2 * np][0] = tmp[0]; bfr[buf][2 * np][1] = tmp[1];        \
            bfr[buf][2 * np + 1][0] = tmp[2]; bfr[buf][2 * np + 1][1] = tmp[3];\
        }                                                                      \
    } while (0)

    STAGE(0, 0);
    for (int kt = 0; kt < ktiles; kt++) {
        const int s = kt & 1;
        if (kt + 1 < ktiles) {
            STAGE(s ^ 1, kt + 1);
            asm volatile("cp.async.wait_group 1;\n");
        } else {
            asm volatile("cp.async.wait_group 0;\n");
        }
        __syncthreads();

        const uint32_t sAu = sA0 + (uint32_t)(s * STAGE_H) * 2u;
        const uint32_t sBu = sAu + (uint32_t)A_ST * 2u;

        LOADFRAG(0, 0);
#pragma unroll
        for (int ks = 0; ks < 4; ks++) {
            const int cur = ks & 1;
            if (ks + 1 < 4) LOADFRAG(cur ^ 1, ks + 1);
#pragma unroll
            for (int mi = 0; mi < 4; mi++)
#pragma unroll
                for (int ni = 0; ni < 8; ni++)
                    mma16n8k16(acc[mi][ni], afr[cur][mi], bfr[cur][ni]);
        }
        __syncthreads();
    }
#undef STAGE
#undef LOADFRAG

    if (!isGemm1) {
        stok[tid]  = g_pair[r0 + tid];
        sgate[tid] = g_gateS[r0 + tid];
    }

    // epilogue: two 64-row phases via smem fp32 (64 x 132)
    float* sC = (float*)smh;
    const int gid = lane >> 2;
    for (int p = 0; p < 2; p++) {
        if (wm == p) {
#pragma unroll
            for (int mi = 0; mi < 4; mi++)
#pragma unroll
                for (int ni = 0; ni < 8; ni++) {
                    int rr = mi * 16 + gid;
                    int cc = wn * 64 + ni * 8 + 2 * tig;
                    sC[rr * 132 + cc]           = acc[mi][ni][0];
                    sC[rr * 132 + cc + 1]       = acc[mi][ni][1];
                    sC[(rr + 8) * 132 + cc]     = acc[mi][ni][2];
                    sC[(rr + 8) * 132 + cc + 1] = acc[mi][ni][3];
                }
        }
        __syncthreads();
#pragma unroll
        for (int j = 0; j < 16; j++) {
            int f = tid + j * 128;               // 2048 float4s = 64x128
            int r = f >> 5, c = (f & 31) << 2;
            int lrow = p * 64 + r;
            int gn = n0 + c;
            float4 cv = *(float4*)(sC + r * 132 + c);
            float4 bv = *(const float4*)(biasp + gn);
            if (isGemm1) {
                __half2 h0 = __floats2half2_rn(gelu_exact(cv.x + bv.x),
                                               gelu_exact(cv.y + bv.y));
                __half2 h1 = __floats2half2_rn(gelu_exact(cv.z + bv.z),
                                               gelu_exact(cv.w + bv.w));
                uint2 pk;
                pk.x = *(uint32_t*)&h0;
                pk.y = *(uint32_t*)&h1;
                *(uint2*)(Out + (size_t)(r0 + lrow) * N + gn) = pk;
            } else {
                int pair = stok[lrow];
                if (pair >= 0) {
                    float g = sgate[lrow];
                    __half2 h0 = __floats2half2_rn((cv.x + bv.x) * g,
                                                   (cv.y + bv.y) * g);
                    __half2 h1 = __floats2half2_rn((cv.z + bv.z) * g,
                                                   (cv.w + bv.w) * g);
                    uint2 pk;
                    pk.x = *(uint32_t*)&h0;
                    pk.y = *(uint32_t*)&h1;
                    *(uint2*)(Out + (size_t)pair * N + gn) = pk;
                }
            }
        }
        __syncthreads();
    }
}

// ---------------------------------------------------------------------------
// Kernel 6: combine 4 half pair contributions per token (fixed order, fp32 acc)
// ---------------------------------------------------------------------------
__global__ void combine_kernel(float* __restrict__ y) {
    const int i = blockIdx.x * 256 + threadIdx.x;  // over T*O/4 groups
    const int t = i >> 8;                          // O/4 = 256 groups per token
    const int c = i & 255;
    const uint2* yp = (const uint2*)g_yph;         // 4 halves per uint2
    size_t base = (size_t)t * TOPK * 256 + c;
    float4 s = make_float4(0.f, 0.f, 0.f, 0.f);
#pragma unroll
    for (int k = 0; k < TOPK; k++) {
        uint2 pk = yp[base + (size_t)k * 256];
        __half2 h0 = *(__half2*)&pk.x;
        __half2 h1 = *(__half2*)&pk.y;
        float2 f0 = __half22float2(h0);
        float2 f1 = __half22float2(h1);
        s.x += f0.x; s.y += f0.y; s.z += f1.x; s.w += f1.y;
    }
    ((float4*)y)[i] = s;
}

// ---------------------------------------------------------------------------
extern "C" void kernel_launch(void* const* d_in, const int* in_sizes, int n_in,
                              void* d_out, int out_size) {
    const float* x     = (const float*)d_in[0];
    const float* gamma = (const float*)d_in[1];
    const float* beta  = (const float*)d_in[2];
    const float* rw    = (const float*)d_in[3];
    const float* rb    = (const float*)d_in[4];
    const float* w1    = (const float*)d_in[5];
    const float* b1    = (const float*)d_in[6];
    const float* w2    = (const float*)d_in[7];
    const float* b2    = (const float*)d_in[8];
    float* y = (float*)d_out;

    __half *xnh_p = nullptr, *hh_p = nullptr, *yph_p = nullptr;
    __half *w1t_p = nullptr, *w2t_p = nullptr;
    int *cnt_p = nullptr, *fill_p = nullptr, *tok_p = nullptr, *pair_p = nullptr;
    cudaGetSymbolAddress((void**)&xnh_p, g_xnh);
    cudaGetSymbolAddress((void**)&hh_p, g_hh);
    cudaGetSymbolAddress((void**)&yph_p, g_yph);
    cudaGetSymbolAddress((void**)&w1t_p, g_w1t);
    cudaGetSymbolAddress((void**)&w2t_p, g_w2t);
    cudaGetSymbolAddress((void**)&cnt_p, g_cnt);
    cudaGetSymbolAddress((void**)&fill_p, g_fill);
    cudaGetSymbolAddress((void**)&tok_p, g_tok);
    cudaGetSymbolAddress((void**)&pair_p, g_pair);

    cudaFuncSetAttribute(moe_gemm_h,
                         cudaFuncAttributeMaxDynamicSharedMemorySize, GEMM_SMEM);

    cudaMemsetAsync(cnt_p, 0, NE * sizeof(int));
    cudaMemsetAsync(fill_p, 0, NE * sizeof(int));
    cudaMemsetAsync(tok_p, 0xFF, MAXROWS * sizeof(int));
    cudaMemsetAsync(pair_p, 0xFF, MAXROWS * sizeof(int));

    dim3 tb(32, 8);
    transpose_h_kernel<<<dim3(H_DIM / 32, D_DIM / 32, NE), tb>>>(w1, w1t_p, D_DIM, H_DIM);
    transpose_h_kernel<<<dim3(O_DIM / 32, H_DIM / 32, NE), tb>>>(w2, w2t_p, H_DIM, O_DIM);

    ln_router_kernel<<<T_TOK / 8, 256>>>(x, gamma, beta, rw, rb);
    offsets_kernel<<<1, 256>>>();
    scatter_kernel<<<T_TOK / 128, 128>>>();

    dim3 g1(H_DIM / 128, MAXTILES);
    dim3 g2(O_DIM / 128, MAXTILES);
    moe_gemm_h<<<g1, 128, GEMM_SMEM>>>(xnh_p, w1t_p, b1, hh_p, D_DIM, H_DIM, 1);
    moe_gemm_h<<<g2, 128, GEMM_SMEM>>>(hh_p, w2t_p, b2, yph_p, H_DIM, O_DIM, 0);

    combine_kernel<<<(T_TOK * O_DIM / 4) / 256, 256>>>(y);
}

// round 16
// speedup vs baseline: 1.1223x; 1.0014x over previous
#include <cuda_runtime.h>
#include <cuda_fp16.h>
#include <cstdint>

#define T_TOK 32768
#define D_DIM 1024
#define H_DIM 2048
#define O_DIM 1024
#define NE 8
#define TOPK 4
#define NPAIR (T_TOK * TOPK)            // 131072
#define MAXROWS (NPAIR + NE * 128)      // 132096
#define MAXTILES (MAXROWS / 128)        // 1032

#define KT 64                            // k-tile
#define LDAH 72                          // halves per smem row (64 + 8 pad)
#define A_ST (128 * LDAH)                // 9216 halves per tile
#define STAGE_H (2 * A_ST)               // 18432 halves per stage
#define GEMM_SMEM (2 * STAGE_H * 2)      // 73728 bytes

// ---- scratch (__device__ globals; allocation-free rule) ----
__device__ __half g_xnh[(size_t)T_TOK * D_DIM];          // 64 MB
__device__ __half g_hh[(size_t)MAXROWS * H_DIM];         // 516 MB
__device__ __half g_yph[(size_t)NPAIR * O_DIM];          // 256 MB (half partials)
__device__ __half g_w1t[(size_t)NE * H_DIM * D_DIM];     // [E][H][D]
__device__ __half g_w2t[(size_t)NE * O_DIM * H_DIM];     // [E][O][H]
__device__ int    g_sel[NPAIR];
__device__ float  g_gval[NPAIR];
__device__ int    g_cnt[NE];
__device__ int    g_fill[NE];
__device__ int    g_off[NE];
__device__ int    g_tok[MAXROWS];
__device__ int    g_pair[MAXROWS];
__device__ float  g_gateS[MAXROWS];
__device__ int    g_texp[MAXTILES];

__device__ __forceinline__ float gelu_exact(float v) { return v * normcdff(v); }

__device__ __forceinline__ void cp16(void* dst, const void* src) {
    unsigned d = (unsigned)__cvta_generic_to_shared(dst);
    asm volatile("cp.async.cg.shared.global [%0], [%1], 16;\n" ::"r"(d), "l"(src));
}

__device__ __forceinline__ void ldm_x4(uint32_t* r, uint32_t saddr) {
    asm volatile("ldmatrix.sync.aligned.m8n8.x4.shared.b16 {%0,%1,%2,%3}, [%4];"
                 : "=r"(r[0]), "=r"(r[1]), "=r"(r[2]), "=r"(r[3]) : "r"(saddr));
}

__device__ __forceinline__ void mma16n8k16(float* d, const uint32_t* a, const uint32_t* b) {
    asm volatile(
        "mma.sync.aligned.m16n8k16.row.col.f32.f16.f16.f32 "
        "{%0,%1,%2,%3}, {%4,%5,%6,%7}, {%8,%9}, {%0,%1,%2,%3};\n"
        : "+f"(d[0]), "+f"(d[1]), "+f"(d[2]), "+f"(d[3])
        : "r"(a[0]), "r"(a[1]), "r"(a[2]), "r"(a[3]), "r"(b[0]), "r"(b[1]));
}

// ---------------------------------------------------------------------------
// Kernel 0: fp32 [R][C] -> half transposed [C][R], per expert (blockIdx.z)
// ---------------------------------------------------------------------------
__global__ void transpose_h_kernel(const float* __restrict__ src,
                                   __half* __restrict__ dst, int R, int C) {
    __shared__ float tile[32][33];
    const float* s = src + (size_t)blockIdx.z * R * C;
    __half* d = dst + (size_t)blockIdx.z * R * C;
    int c0 = blockIdx.x * 32, r0 = blockIdx.y * 32;
    int tx = threadIdx.x, ty = threadIdx.y;  // (32, 8)
#pragma unroll
    for (int j = 0; j < 4; j++)
        tile[ty + j * 8][tx] = s[(size_t)(r0 + ty + j * 8) * C + c0 + tx];
    __syncthreads();
#pragma unroll
    for (int j = 0; j < 4; j++)
        d[(size_t)(c0 + ty + j * 8) * R + r0 + tx] =
            __float2half_rn(tile[tx][ty + j * 8]);
}

// ---------------------------------------------------------------------------
// Kernel 1: warp-per-token LayerNorm + router + top-4 softmax + fused count.
// Vectorized: float4 loads of x/gamma/beta, uint2 (4-half) stores of xn.
// Lane owns idx = i*128 + lane*4 + q,  i = 0..7, q = 0..3.
// ---------------------------------------------------------------------------
__global__ __launch_bounds__(256) void ln_router_kernel(
    const float* __restrict__ x, const float* __restrict__ gamma,
    const float* __restrict__ beta, const float* __restrict__ rw,
    const float* __restrict__ rb) {
    __shared__ int hist[NE];
    const int tid = threadIdx.x;
    const int warp = tid >> 5, lane = tid & 31;
    if (tid < NE) hist[tid] = 0;
    __syncthreads();

    const int t = blockIdx.x * 8 + warp;
    const float4* xr4 = (const float4*)(x + (size_t)t * D_DIM);

    float4 v[8];
    float s = 0.f, ss = 0.f;
#pragma unroll
    for (int i = 0; i < 8; i++) {
        float4 val = xr4[i * 32 + lane];
        v[i] = val;
        s += val.x + val.y + val.z + val.w;
        ss += val.x * val.x + val.y * val.y + val.z * val.z + val.w * val.w;
    }
#pragma unroll
    for (int o = 16; o > 0; o >>= 1) {
        s += __shfl_xor_sync(0xffffffffu, s, o);
        ss += __shfl_xor_sync(0xffffffffu, ss, o);
    }
    const float mu = s * (1.f / D_DIM);
    const float var = ss * (1.f / D_DIM) - mu * mu;
    const float rstd = rsqrtf(var + 1e-5f);

    float lg[NE];
#pragma unroll
    for (int e = 0; e < NE; e++) lg[e] = 0.f;
    uint2* xnout = (uint2*)(g_xnh + (size_t)t * D_DIM);
    const float4* g4 = (const float4*)gamma;
    const float4* b4 = (const float4*)beta;
#pragma unroll
    for (int i = 0; i < 8; i++) {
        const int v4i = i * 32 + lane;          // float4 index; elem base = 4*v4i
        float4 gm = g4[v4i];
        float4 bt = b4[v4i];
        float xn0 = (v[i].x - mu) * rstd * gm.x + bt.x;
        float xn1 = (v[i].y - mu) * rstd * gm.y + bt.y;
        float xn2 = (v[i].z - mu) * rstd * gm.z + bt.z;
        float xn3 = (v[i].w - mu) * rstd * gm.w + bt.w;
        __half2 h0 = __floats2half2_rn(xn0, xn1);
        __half2 h1 = __floats2half2_rn(xn2, xn3);
        uint2 pk;
        pk.x = *(uint32_t*)&h0;
        pk.y = *(uint32_t*)&h1;
        xnout[v4i] = pk;
        const float4* w4 = (const float4*)(rw + (size_t)(4 * v4i) * NE);
        // rows of rw for the 4 consecutive idx: 8 float4s, contiguous
        float4 wa, wb;
        wa = w4[0]; wb = w4[1];
        lg[0] += xn0 * wa.x; lg[1] += xn0 * wa.y; lg[2] += xn0 * wa.z; lg[3] += xn0 * wa.w;
        lg[4] += xn0 * wb.x; lg[5] += xn0 * wb.y; lg[6] += xn0 * wb.z; lg[7] += xn0 * wb.w;
        wa = w4[2]; wb = w4[3];
        lg[0] += xn1 * wa.x; lg[1] += xn1 * wa.y; lg[2] += xn1 * wa.z; lg[3] += xn1 * wa.w;
        lg[4] += xn1 * wb.x; lg[5] += xn1 * wb.y; lg[6] += xn1 * wb.z; lg[7] += xn1 * wb.w;
        wa = w4[4]; wb = w4[5];
        lg[0] += xn2 * wa.x; lg[1] += xn2 * wa.y; lg[2] += xn2 * wa.z; lg[3] += xn2 * wa.w;
        lg[4] += xn2 * wb.x; lg[5] += xn2 * wb.y; lg[6] += xn2 * wb.z; lg[7] += xn2 * wb.w;
        wa = w4[6]; wb = w4[7];
        lg[0] += xn3 * wa.x; lg[1] += xn3 * wa.y; lg[2] += xn3 * wa.z; lg[3] += xn3 * wa.w;
        lg[4] += xn3 * wb.x; lg[5] += xn3 * wb.y; lg[6] += xn3 * wb.z; lg[7] += xn3 * wb.w;
    }
#pragma unroll
    for (int e = 0; e < NE; e++)
#pragma unroll
        for (int o = 16; o > 0; o >>= 1)
            lg[e] += __shfl_xor_sync(0xffffffffu, lg[e], o);

    if (lane == 0) {
        float logit[NE];
#pragma unroll
        for (int e = 0; e < NE; e++) logit[e] = lg[e] + rb[e];
        int sel[TOPK]; float mv[TOPK]; bool used[NE];
#pragma unroll
        for (int e = 0; e < NE; e++) used[e] = false;
#pragma unroll
        for (int k = 0; k < TOPK; k++) {
            int bi = 0; float bv = -3.4e38f;
#pragma unroll
            for (int e = 0; e < NE; e++)
                if (!used[e] && logit[e] > bv) { bv = logit[e]; bi = e; }
            used[bi] = true; sel[k] = bi; mv[k] = bv;
        }
        const float m = mv[0];
        float den = 0.f, ex[TOPK];
#pragma unroll
        for (int k = 0; k < TOPK; k++) { ex[k] = expf(mv[k] - m); den += ex[k]; }
#pragma unroll
        for (int k = 0; k < TOPK; k++) {
            g_sel[t * TOPK + k]  = sel[k];
            g_gval[t * TOPK + k] = ex[k] / den;
            atomicAdd(&hist[sel[k]], 1);
        }
    }
    __syncthreads();
    if (tid < NE) atomicAdd(&g_cnt[tid], hist[tid]);
}

// ---------------------------------------------------------------------------
// Kernel 3: offsets (1 block): prefix, texp fill, AND pad-slot init
// (replaces the two 528KB memsets of g_tok / g_pair)
// ---------------------------------------------------------------------------
__global__ void offsets_kernel() {
    __shared__ int tstart[NE + 1];
    __shared__ int padlo[NE], padhi[NE];
    const int tid = threadIdx.x;  // 256
    if (tid == 0) {
        int off = 0, tile = 0;
        for (int e = 0; e < NE; e++) {
            g_off[e] = off;
            tstart[e] = tile;
            int tiles_e = (g_cnt[e] + 127) >> 7;
            tile += tiles_e;
            padlo[e] = off + g_cnt[e];
            padhi[e] = off + (tiles_e << 7);
            off += tiles_e << 7;
        }
        tstart[NE] = tile;
    }
    __syncthreads();
    for (int i = tid; i < MAXTILES; i += 256) {
        int e = -1;
#pragma unroll
        for (int q = 0; q < NE; q++)
            if (i >= tstart[q] && i < tstart[q + 1]) e = q;
        g_texp[i] = e;
    }
    // pad slots: pair=-1 (discard in GEMM2), tok=0 (safe gather in GEMM1)
#pragma unroll
    for (int e = 0; e < NE; e++) {
        for (int p = padlo[e] + tid; p < padhi[e]; p += 256) {
            g_pair[p] = -1;
            g_tok[p] = 0;
        }
    }
}

// ---------------------------------------------------------------------------
// Kernel 4: scatter
// ---------------------------------------------------------------------------
__global__ void scatter_kernel() {
    __shared__ int lcnt[NE], lbase[NE];
    const int tid = threadIdx.x;  // 128
    const int t = blockIdx.x * 128 + tid;
    if (tid < NE) lcnt[tid] = 0;
    __syncthreads();
    int myidx[TOPK], mye[TOPK]; float myg[TOPK];
#pragma unroll
    for (int k = 0; k < TOPK; k++) {
        int e = g_sel[t * TOPK + k];
        mye[k] = e;
        myg[k] = g_gval[t * TOPK + k];
        myidx[k] = atomicAdd(&lcnt[e], 1);
    }
    __syncthreads();
    if (tid < NE) lbase[tid] = atomicAdd(&g_fill[tid], lcnt[tid]);
    __syncthreads();
#pragma unroll
    for (int k = 0; k < TOPK; k++) {
        int pos = g_off[mye[k]] + lbase[mye[k]] + myidx[k];
        g_tok[pos]   = t;
        g_pair[pos]  = t * TOPK + k;
        g_gateS[pos] = myg[k];
    }
}

// ---------------------------------------------------------------------------
// Kernel 5: fp16 GEMM, 128x128 CTA tile, K-tile 64, 4 warps (2x2), warp 64x64,
// mma.m16n8k16 + ldmatrix with register double-buffered fragments,
// 2-stage cp.async (stores before wait), 2 CTAs/SM.  [R12 exact, frozen]
// ---------------------------------------------------------------------------
__global__ __launch_bounds__(128, 2) void moe_gemm_h(
    const __half* __restrict__ A, const __half* __restrict__ B,
    const float* __restrict__ bias, __half* __restrict__ Out,
    int K, int N, int isGemm1) {
    extern __shared__ __half smh[];
    __shared__ int   stok[128];
    __shared__ float sgate[128];

    const int tid = threadIdx.x;     // 128
    const int warp = tid >> 5;
    const int lane = tid & 31;
    const int tig = lane & 3;
    const int wm = warp >> 1;        // 0..1
    const int wn = warp & 1;         // 0..1
    const int te = g_texp[blockIdx.y];
    if (te < 0) return;
    const int r0 = blockIdx.y * 128;
    const int n0 = blockIdx.x * 128;
    const __half* Bp = B + (size_t)te * K * N;   // [N][K] n-major
    const float* biasp = bias + (size_t)te * N;

    if (isGemm1) {
        stok[tid] = g_tok[r0 + tid];
        __syncthreads();
    }

    const int srow = tid >> 3, sc8 = (tid & 7) * 8;
    const __half* asrc[8];
#pragma unroll
    for (int j = 0; j < 8; j++) {
        int r = srow + j * 16;
        if (isGemm1) {
            int tk = stok[r]; if (tk < 0) tk = 0;
            asrc[j] = g_xnh + (size_t)tk * D_DIM + sc8;
        } else {
            asrc[j] = A + (size_t)(r0 + r) * K + sc8;
        }
    }
    const __half* bsrc[8];
#pragma unroll
    for (int j = 0; j < 8; j++) {
        int r = srow + j * 16;
        bsrc[j] = Bp + (size_t)(n0 + r) * K + sc8;
    }

    float acc[4][8][4];
#pragma unroll
    for (int mi = 0; mi < 4; mi++)
#pragma unroll
        for (int ni = 0; ni < 8; ni++)
#pragma unroll
            for (int q = 0; q < 4; q++) acc[mi][ni][q] = 0.f;

    const uint32_t sA0 = (uint32_t)__cvta_generic_to_shared(smh);
    const int a_lr = (lane & 7) + ((lane >> 3) & 1) * 8;
    const int a_lc = ((lane >> 4) & 1) * 8;
    const int b_lr = (lane & 7) + ((lane >> 4) & 1) * 8;
    const int b_lc = ((lane >> 3) & 1) * 8;

    const int ktiles = K / KT;

#define STAGE(s, kt)                                                   \
    do {                                                               \
        __half* sa_ = smh + (s) * STAGE_H;                             \
        __half* sb_ = sa_ + A_ST;                                      \
        _Pragma("unroll")                                              \
        for (int j = 0; j < 8; j++) {                                  \
            int r = srow + j * 16;                                     \
            cp16(sa_ + r * LDAH + sc8, asrc[j] + (kt) * KT);           \
            cp16(sb_ + r * LDAH + sc8, bsrc[j] + (kt) * KT);           \
        }                                                              \
        asm volatile("cp.async.commit_group;\n");                      \
    } while (0)

    uint32_t afr[2][4][4];
    uint32_t bfr[2][8][2];

#define LOADFRAG(buf, ks_)                                                     \
    do {                                                                       \
        _Pragma("unroll")                                                      \
        for (int mi = 0; mi < 4; mi++)                                         \
            ldm_x4(afr[buf][mi],                                               \
                   sAu + (uint32_t)(((wm * 64 + mi * 16 + a_lr) * LDAH +       \
                                     (ks_) * 16 + a_lc) * 2));                 \
        _Pragma("unroll")                                                      \
        for (int np = 0; np < 4; np++) {                                       \
            uint32_t tmp[4];                                                   \
            ldm_x4(tmp,                                                        \
                   sBu + (uint32_t)(((wn * 64 + np * 16 + b_lr) * LDAH +       \
                                     (ks_) * 16 + b_lc) * 2));                 \
            bfr[buf][2 * np][0] = tmp[0]; bfr[buf][2 * np][1] = tmp[1];        \
            bfr[buf][2 * np + 1][0] = tmp[2]; bfr[buf][2 * np + 1][1] = tmp[3];\
        }                                                                      \
    } while (0)

    STAGE(0, 0);
    for (int kt = 0; kt < ktiles; kt++) {
        const int s = kt & 1;
        if (kt + 1 < ktiles) {
            STAGE(s ^ 1, kt + 1);
            asm volatile("cp.async.wait_group 1;\n");
        } else {
            asm volatile("cp.async.wait_group 0;\n");
        }
        __syncthreads();

        const uint32_t sAu = sA0 + (uint32_t)(s * STAGE_H) * 2u;
        const uint32_t sBu = sAu + (uint32_t)A_ST * 2u;

        LOADFRAG(0, 0);
#pragma unroll
        for (int ks = 0; ks < 4; ks++) {
            const int cur = ks & 1;
            if (ks + 1 < 4) LOADFRAG(cur ^ 1, ks + 1);
#pragma unroll
            for (int mi = 0; mi < 4; mi++)
#pragma unroll
                for (int ni = 0; ni < 8; ni++)
                    mma16n8k16(acc[mi][ni], afr[cur][mi], bfr[cur][ni]);
        }
        __syncthreads();
    }
#undef STAGE
#undef LOADFRAG

    if (!isGemm1) {
        stok[tid]  = g_pair[r0 + tid];
        sgate[tid] = g_gateS[r0 + tid];
    }

    // epilogue: two 64-row phases via smem fp32 (64 x 132)
    float* sC = (float*)smh;
    const int gid = lane >> 2;
    for (int p = 0; p < 2; p++) {
        if (wm == p) {
#pragma unroll
            for (int mi = 0; mi < 4; mi++)
#pragma unroll
                for (int ni = 0; ni < 8; ni++) {
                    int rr = mi * 16 + gid;
                    int cc = wn * 64 + ni * 8 + 2 * tig;
                    sC[rr * 132 + cc]           = acc[mi][ni][0];
                    sC[rr * 132 + cc + 1]       = acc[mi][ni][1];
                    sC[(rr + 8) * 132 + cc]     = acc[mi][ni][2];
                    sC[(rr + 8) * 132 + cc + 1] = acc[mi][ni][3];
                }
        }
        __syncthreads();
#pragma unroll
        for (int j = 0; j < 16; j++) {
            int f = tid + j * 128;               // 2048 float4s = 64x128
            int r = f >> 5, c = (f & 31) << 2;
            int lrow = p * 64 + r;
            int gn = n0 + c;
            float4 cv = *(float4*)(sC + r * 132 + c);
            float4 bv = *(const float4*)(biasp + gn);
            if (isGemm1) {
                __half2 h0 = __floats2half2_rn(gelu_exact(cv.x + bv.x),
                                               gelu_exact(cv.y + bv.y));
                __half2 h1 = __floats2half2_rn(gelu_exact(cv.z + bv.z),
                                               gelu_exact(cv.w + bv.w));
                uint2 pk;
                pk.x = *(uint32_t*)&h0;
                pk.y = *(uint32_t*)&h1;
                *(uint2*)(Out + (size_t)(r0 + lrow) * N + gn) = pk;
            } else {
                int pair = stok[lrow];
                if (pair >= 0) {
                    float g = sgate[lrow];
                    __half2 h0 = __floats2half2_rn((cv.x + bv.x) * g,
                                                   (cv.y + bv.y) * g);
                    __half2 h1 = __floats2half2_rn((cv.z + bv.z) * g,
                                                   (cv.w + bv.w) * g);
                    uint2 pk;
                    pk.x = *(uint32_t*)&h0;
                    pk.y = *(uint32_t*)&h1;
                    *(uint2*)(Out + (size_t)pair * N + gn) = pk;
                }
            }
        }
        __syncthreads();
    }
}

// ---------------------------------------------------------------------------
// Kernel 6: combine 4 half pair contributions per token (fixed order, fp32 acc)
// ---------------------------------------------------------------------------
__global__ void combine_kernel(float* __restrict__ y) {
    const int i = blockIdx.x * 256 + threadIdx.x;  // over T*O/4 groups
    const int t = i >> 8;                          // O/4 = 256 groups per token
    const int c = i & 255;
    const uint2* yp = (const uint2*)g_yph;         // 4 halves per uint2
    size_t base = (size_t)t * TOPK * 256 + c;
    float4 s = make_float4(0.f, 0.f, 0.f, 0.f);
#pragma unroll
    for (int k = 0; k < TOPK; k++) {
        uint2 pk = yp[base + (size_t)k * 256];
        __half2 h0 = *(__half2*)&pk.x;
        __half2 h1 = *(__half2*)&pk.y;
        float2 f0 = __half22float2(h0);
        float2 f1 = __half22float2(h1);
        s.x += f0.x; s.y += f0.y; s.z += f1.x; s.w += f1.y;
    }
    ((float4*)y)[i] = s;
}

// ---------------------------------------------------------------------------
extern "C" void kernel_launch(void* const* d_in, const int* in_sizes, int n_in,
                              void* d_out, int out_size) {
    const float* x     = (const float*)d_in[0];
    const float* gamma = (const float*)d_in[1];
    const float* beta  = (const float*)d_in[2];
    const float* rw    = (const float*)d_in[3];
    const float* rb    = (const float*)d_in[4];
    const float* w1    = (const float*)d_in[5];
    const float* b1    = (const float*)d_in[6];
    const float* w2    = (const float*)d_in[7];
    const float* b2    = (const float*)d_in[8];
    float* y = (float*)d_out;

    __half *xnh_p = nullptr, *hh_p = nullptr, *yph_p = nullptr;
    __half *w1t_p = nullptr, *w2t_p = nullptr;
    int *cnt_p = nullptr, *fill_p = nullptr;
    cudaGetSymbolAddress((void**)&xnh_p, g_xnh);
    cudaGetSymbolAddress((void**)&hh_p, g_hh);
    cudaGetSymbolAddress((void**)&yph_p, g_yph);
    cudaGetSymbolAddress((void**)&w1t_p, g_w1t);
    cudaGetSymbolAddress((void**)&w2t_p, g_w2t);
    cudaGetSymbolAddress((void**)&cnt_p, g_cnt);
    cudaGetSymbolAddress((void**)&fill_p, g_fill);

    cudaFuncSetAttribute(moe_gemm_h,
                         cudaFuncAttributeMaxDynamicSharedMemorySize, GEMM_SMEM);

    cudaMemsetAsync(cnt_p, 0, NE * sizeof(int));
    cudaMemsetAsync(fill_p, 0, NE * sizeof(int));

    dim3 tb(32, 8);
    transpose_h_kernel<<<dim3(H_DIM / 32, D_DIM / 32, NE), tb>>>(w1, w1t_p, D_DIM, H_DIM);
    transpose_h_kernel<<<dim3(O_DIM / 32, H_DIM / 32, NE), tb>>>(w2, w2t_p, H_DIM, O_DIM);

    ln_router_kernel<<<T_TOK / 8, 256>>>(x, gamma, beta, rw, rb);
    offsets_kernel<<<1, 256>>>();
    scatter_kernel<<<T_TOK / 128, 128>>>();

    dim3 g1(H_DIM / 128, MAXTILES);
    dim3 g2(O_DIM / 128, MAXTILES);
    moe_gemm_h<<<g1, 128, GEMM_SMEM>>>(xnh_p, w1t_p, b1, hh_p, D_DIM, H_DIM, 1);
    moe_gemm_h<<<g2, 128, GEMM_SMEM>>>(hh_p, w2t_p, b2, yph_p, H_DIM, O_DIM, 0);

    combine_kernel<<<(T_TOK * O_DIM / 4) / 256, 256>>>(y);
}

// round 17
// speedup vs baseline: 1.1386x; 1.0145x over previous
#include <cuda_runtime.h>
#include <cuda_fp16.h>
#include <cstdint>

#define T_TOK 32768
#define D_DIM 1024
#define H_DIM 2048
#define O_DIM 1024
#define NE 8
#define TOPK 4
#define NPAIR (T_TOK * TOPK)            // 131072
#define MAXROWS (NPAIR + NE * 128)      // 132096
#define MAXTILES (MAXROWS / 128)        // 1032

#define KT 64                            // k-tile
#define LDAH 72                          // halves per smem row (64 + 8 pad)
#define A_ST (128 * LDAH)                // 9216 halves per tile
#define STAGE_H (2 * A_ST)               // 18432 halves per stage
#define GEMM_SMEM (2 * STAGE_H * 2)      // 73728 bytes

// ---- scratch (__device__ globals; allocation-free rule) ----
__device__ __half g_xnh[(size_t)T_TOK * D_DIM];          // 64 MB
__device__ __half g_hh[(size_t)MAXROWS * H_DIM];         // 516 MB
__device__ __half g_yph[(size_t)NPAIR * O_DIM];          // 256 MB (half partials)
__device__ __half g_w1t[(size_t)NE * H_DIM * D_DIM];     // [E][H][D]
__device__ __half g_w2t[(size_t)NE * O_DIM * H_DIM];     // [E][O][H]
__device__ int    g_sel[NPAIR];
__device__ float  g_gval[NPAIR];
__device__ int    g_cnt[NE];
__device__ int    g_fill[NE];
__device__ int    g_off[NE];
__device__ int    g_tok[MAXROWS];
__device__ int    g_pair[MAXROWS];
__device__ float  g_gateS[MAXROWS];
__device__ int    g_texp[MAXTILES];

__device__ __forceinline__ float gelu_exact(float v) { return v * normcdff(v); }

__device__ __forceinline__ void cp16(void* dst, const void* src) {
    unsigned d = (unsigned)__cvta_generic_to_shared(dst);
    asm volatile("cp.async.cg.shared.global [%0], [%1], 16;\n" ::"r"(d), "l"(src));
}

__device__ __forceinline__ void ldm_x4(uint32_t* r, uint32_t saddr) {
    asm volatile("ldmatrix.sync.aligned.m8n8.x4.shared.b16 {%0,%1,%2,%3}, [%4];"
                 : "=r"(r[0]), "=r"(r[1]), "=r"(r[2]), "=r"(r[3]) : "r"(saddr));
}

__device__ __forceinline__ void mma16n8k16(float* d, const uint32_t* a, const uint32_t* b) {
    asm volatile(
        "mma.sync.aligned.m16n8k16.row.col.f32.f16.f16.f32 "
        "{%0,%1,%2,%3}, {%4,%5,%6,%7}, {%8,%9}, {%0,%1,%2,%3};\n"
        : "+f"(d[0]), "+f"(d[1]), "+f"(d[2]), "+f"(d[3])
        : "r"(a[0]), "r"(a[1]), "r"(a[2]), "r"(a[3]), "r"(b[0]), "r"(b[1]));
}

// ---------------------------------------------------------------------------
// Kernel 0: fp32 [R][C] -> half transposed [C][R], per expert (blockIdx.z)
// ---------------------------------------------------------------------------
__global__ void transpose_h_kernel(const float* __restrict__ src,
                                   __half* __restrict__ dst, int R, int C) {
    __shared__ float tile[32][33];
    const float* s = src + (size_t)blockIdx.z * R * C;
    __half* d = dst + (size_t)blockIdx.z * R * C;
    int c0 = blockIdx.x * 32, r0 = blockIdx.y * 32;
    int tx = threadIdx.x, ty = threadIdx.y;  // (32, 8)
#pragma unroll
    for (int j = 0; j < 4; j++)
        tile[ty + j * 8][tx] = s[(size_t)(r0 + ty + j * 8) * C + c0 + tx];
    __syncthreads();
#pragma unroll
    for (int j = 0; j < 4; j++)
        d[(size_t)(c0 + ty + j * 8) * R + r0 + tx] =
            __float2half_rn(tile[tx][ty + j * 8]);
}

// ---------------------------------------------------------------------------
// Kernel 1: warp-per-token LayerNorm + router + top-4 softmax + fused count.
// Vectorized: float4 loads of x/gamma/beta, uint2 (4-half) stores of xn.
// ---------------------------------------------------------------------------
__global__ __launch_bounds__(256) void ln_router_kernel(
    const float* __restrict__ x, const float* __restrict__ gamma,
    const float* __restrict__ beta, const float* __restrict__ rw,
    const float* __restrict__ rb) {
    __shared__ int hist[NE];
    const int tid = threadIdx.x;
    const int warp = tid >> 5, lane = tid & 31;
    if (tid < NE) hist[tid] = 0;
    __syncthreads();

    const int t = blockIdx.x * 8 + warp;
    const float4* xr4 = (const float4*)(x + (size_t)t * D_DIM);

    float4 v[8];
    float s = 0.f, ss = 0.f;
#pragma unroll
    for (int i = 0; i < 8; i++) {
        float4 val = xr4[i * 32 + lane];
        v[i] = val;
        s += val.x + val.y + val.z + val.w;
        ss += val.x * val.x + val.y * val.y + val.z * val.z + val.w * val.w;
    }
#pragma unroll
    for (int o = 16; o > 0; o >>= 1) {
        s += __shfl_xor_sync(0xffffffffu, s, o);
        ss += __shfl_xor_sync(0xffffffffu, ss, o);
    }
    const float mu = s * (1.f / D_DIM);
    const float var = ss * (1.f / D_DIM) - mu * mu;
    const float rstd = rsqrtf(var + 1e-5f);

    float lg[NE];
#pragma unroll
    for (int e = 0; e < NE; e++) lg[e] = 0.f;
    uint2* xnout = (uint2*)(g_xnh + (size_t)t * D_DIM);
    const float4* g4 = (const float4*)gamma;
    const float4* b4 = (const float4*)beta;
#pragma unroll
    for (int i = 0; i < 8; i++) {
        const int v4i = i * 32 + lane;
        float4 gm = g4[v4i];
        float4 bt = b4[v4i];
        float xn0 = (v[i].x - mu) * rstd * gm.x + bt.x;
        float xn1 = (v[i].y - mu) * rstd * gm.y + bt.y;
        float xn2 = (v[i].z - mu) * rstd * gm.z + bt.z;
        float xn3 = (v[i].w - mu) * rstd * gm.w + bt.w;
        __half2 h0 = __floats2half2_rn(xn0, xn1);
        __half2 h1 = __floats2half2_rn(xn2, xn3);
        uint2 pk;
        pk.x = *(uint32_t*)&h0;
        pk.y = *(uint32_t*)&h1;
        xnout[v4i] = pk;
        const float4* w4 = (const float4*)(rw + (size_t)(4 * v4i) * NE);
        float4 wa, wb;
        wa = w4[0]; wb = w4[1];
        lg[0] += xn0 * wa.x; lg[1] += xn0 * wa.y; lg[2] += xn0 * wa.z; lg[3] += xn0 * wa.w;
        lg[4] += xn0 * wb.x; lg[5] += xn0 * wb.y; lg[6] += xn0 * wb.z; lg[7] += xn0 * wb.w;
        wa = w4[2]; wb = w4[3];
        lg[0] += xn1 * wa.x; lg[1] += xn1 * wa.y; lg[2] += xn1 * wa.z; lg[3] += xn1 * wa.w;
        lg[4] += xn1 * wb.x; lg[5] += xn1 * wb.y; lg[6] += xn1 * wb.z; lg[7] += xn1 * wb.w;
        wa = w4[4]; wb = w4[5];
        lg[0] += xn2 * wa.x; lg[1] += xn2 * wa.y; lg[2] += xn2 * wa.z; lg[3] += xn2 * wa.w;
        lg[4] += xn2 * wb.x; lg[5] += xn2 * wb.y; lg[6] += xn2 * wb.z; lg[7] += xn2 * wb.w;
        wa = w4[6]; wb = w4[7];
        lg[0] += xn3 * wa.x; lg[1] += xn3 * wa.y; lg[2] += xn3 * wa.z; lg[3] += xn3 * wa.w;
        lg[4] += xn3 * wb.x; lg[5] += xn3 * wb.y; lg[6] += xn3 * wb.z; lg[7] += xn3 * wb.w;
    }
#pragma unroll
    for (int e = 0; e < NE; e++)
#pragma unroll
        for (int o = 16; o > 0; o >>= 1)
            lg[e] += __shfl_xor_sync(0xffffffffu, lg[e], o);

    if (lane == 0) {
        float logit[NE];
#pragma unroll
        for (int e = 0; e < NE; e++) logit[e] = lg[e] + rb[e];
        int sel[TOPK]; float mv[TOPK]; bool used[NE];
#pragma unroll
        for (int e = 0; e < NE; e++) used[e] = false;
#pragma unroll
        for (int k = 0; k < TOPK; k++) {
            int bi = 0; float bv = -3.4e38f;
#pragma unroll
            for (int e = 0; e < NE; e++)
                if (!used[e] && logit[e] > bv) { bv = logit[e]; bi = e; }
            used[bi] = true; sel[k] = bi; mv[k] = bv;
        }
        const float m = mv[0];
        float den = 0.f, ex[TOPK];
#pragma unroll
        for (int k = 0; k < TOPK; k++) { ex[k] = expf(mv[k] - m); den += ex[k]; }
#pragma unroll
        for (int k = 0; k < TOPK; k++) {
            g_sel[t * TOPK + k]  = sel[k];
            g_gval[t * TOPK + k] = ex[k] / den;
            atomicAdd(&hist[sel[k]], 1);
        }
    }
    __syncthreads();
    if (tid < NE) atomicAdd(&g_cnt[tid], hist[tid]);
}

// ---------------------------------------------------------------------------
// Kernel 3: offsets (1 block): prefix, texp fill, AND pad-slot init
// ---------------------------------------------------------------------------
__global__ void offsets_kernel() {
    __shared__ int tstart[NE + 1];
    __shared__ int padlo[NE], padhi[NE];
    const int tid = threadIdx.x;  // 256
    if (tid == 0) {
        int off = 0, tile = 0;
        for (int e = 0; e < NE; e++) {
            g_off[e] = off;
            tstart[e] = tile;
            int tiles_e = (g_cnt[e] + 127) >> 7;
            tile += tiles_e;
            padlo[e] = off + g_cnt[e];
            padhi[e] = off + (tiles_e << 7);
            off += tiles_e << 7;
        }
        tstart[NE] = tile;
    }
    __syncthreads();
    for (int i = tid; i < MAXTILES; i += 256) {
        int e = -1;
#pragma unroll
        for (int q = 0; q < NE; q++)
            if (i >= tstart[q] && i < tstart[q + 1]) e = q;
        g_texp[i] = e;
    }
#pragma unroll
    for (int e = 0; e < NE; e++) {
        for (int p = padlo[e] + tid; p < padhi[e]; p += 256) {
            g_pair[p] = -1;
            g_tok[p] = 0;
        }
    }
}

// ---------------------------------------------------------------------------
// Kernel 4: scatter
// ---------------------------------------------------------------------------
__global__ void scatter_kernel() {
    __shared__ int lcnt[NE], lbase[NE];
    const int tid = threadIdx.x;  // 128
    const int t = blockIdx.x * 128 + tid;
    if (tid < NE) lcnt[tid] = 0;
    __syncthreads();
    int myidx[TOPK], mye[TOPK]; float myg[TOPK];
#pragma unroll
    for (int k = 0; k < TOPK; k++) {
        int e = g_sel[t * TOPK + k];
        mye[k] = e;
        myg[k] = g_gval[t * TOPK + k];
        myidx[k] = atomicAdd(&lcnt[e], 1);
    }
    __syncthreads();
    if (tid < NE) lbase[tid] = atomicAdd(&g_fill[tid], lcnt[tid]);
    __syncthreads();
#pragma unroll
    for (int k = 0; k < TOPK; k++) {
        int pos = g_off[mye[k]] + lbase[mye[k]] + myidx[k];
        g_tok[pos]   = t;
        g_pair[pos]  = t * TOPK + k;
        g_gateS[pos] = myg[k];
    }
}

// ---------------------------------------------------------------------------
// Kernel 5: fp16 GEMM [R12 mainloop frozen]; epilogue prep hoisted before the
// final wait_group to hide its DRAM latency under the pipeline drain.
// ---------------------------------------------------------------------------
__global__ __launch_bounds__(128, 2) void moe_gemm_h(
    const __half* __restrict__ A, const __half* __restrict__ B,
    const float* __restrict__ bias, __half* __restrict__ Out,
    int K, int N, int isGemm1) {
    extern __shared__ __half smh[];
    __shared__ int   stok[128];
    __shared__ float sgate[128];

    const int tid = threadIdx.x;     // 128
    const int warp = tid >> 5;
    const int lane = tid & 31;
    const int tig = lane & 3;
    const int wm = warp >> 1;        // 0..1
    const int wn = warp & 1;         // 0..1
    const int te = g_texp[blockIdx.y];
    if (te < 0) return;
    const int r0 = blockIdx.y * 128;
    const int n0 = blockIdx.x * 128;
    const __half* Bp = B + (size_t)te * K * N;   // [N][K] n-major
    const float* biasp = bias + (size_t)te * N;

    if (isGemm1) {
        stok[tid] = g_tok[r0 + tid];
        __syncthreads();
    }

    const int srow = tid >> 3, sc8 = (tid & 7) * 8;
    const __half* asrc[8];
#pragma unroll
    for (int j = 0; j < 8; j++) {
        int r = srow + j * 16;
        if (isGemm1) {
            int tk = stok[r]; if (tk < 0) tk = 0;
            asrc[j] = g_xnh + (size_t)tk * D_DIM + sc8;
        } else {
            asrc[j] = A + (size_t)(r0 + r) * K + sc8;
        }
    }
    const __half* bsrc[8];
#pragma unroll
    for (int j = 0; j < 8; j++) {
        int r = srow + j * 16;
        bsrc[j] = Bp + (size_t)(n0 + r) * K + sc8;
    }

    float acc[4][8][4];
#pragma unroll
    for (int mi = 0; mi < 4; mi++)
#pragma unroll
        for (int ni = 0; ni < 8; ni++)
#pragma unroll
            for (int q = 0; q < 4; q++) acc[mi][ni][q] = 0.f;

    const uint32_t sA0 = (uint32_t)__cvta_generic_to_shared(smh);
    const int a_lr = (lane & 7) + ((lane >> 3) & 1) * 8;
    const int a_lc = ((lane >> 4) & 1) * 8;
    const int b_lr = (lane & 7) + ((lane >> 4) & 1) * 8;
    const int b_lc = ((lane >> 3) & 1) * 8;

    const int ktiles = K / KT;

#define STAGE(s, kt)                                                   \
    do {                                                               \
        __half* sa_ = smh + (s) * STAGE_H;                             \
        __half* sb_ = sa_ + A_ST;                                      \
        _Pragma("unroll")                                              \
        for (int j = 0; j < 8; j++) {                                  \
            int r = srow + j * 16;                                     \
            cp16(sa_ + r * LDAH + sc8, asrc[j] + (kt) * KT);           \
            cp16(sb_ + r * LDAH + sc8, bsrc[j] + (kt) * KT);           \
        }                                                              \
        asm volatile("cp.async.commit_group;\n");                      \
    } while (0)

    uint32_t afr[2][4][4];
    uint32_t bfr[2][8][2];

#define LOADFRAG(buf, ks_)                                                     \
    do {                                                                       \
        _Pragma("unroll")                                                      \
        for (int mi = 0; mi < 4; mi++)                                         \
            ldm_x4(afr[buf][mi],                                               \
                   sAu + (uint32_t)(((wm * 64 + mi * 16 + a_lr) * LDAH +       \
                                     (ks_) * 16 + a_lc) * 2));                 \
        _Pragma("unroll")                                                      \
        for (int np = 0; np < 4; np++) {                                       \
            uint32_t tmp[4];                                                   \
            ldm_x4(tmp,                                                        \
                   sBu + (uint32_t)(((wn * 64 + np * 16 + b_lr) * LDAH +       \
                                     (ks_) * 16 + b_lc) * 2));                 \
            bfr[buf][2 * np][0] = tmp[0]; bfr[buf][2 * np][1] = tmp[1];        \
            bfr[buf][2 * np + 1][0] = tmp[2]; bfr[buf][2 * np + 1][1] = tmp[3];\
        }                                                                      \
    } while (0)

    STAGE(0, 0);
    for (int kt = 0; kt < ktiles; kt++) {
        const int s = kt & 1;
        if (kt + 1 < ktiles) {
            STAGE(s ^ 1, kt + 1);
            asm volatile("cp.async.wait_group 1;\n");
        } else {
            // hoist epilogue table loads so their latency hides under drain
            if (!isGemm1) {
                stok[tid]  = g_pair[r0 + tid];
                sgate[tid] = g_gateS[r0 + tid];
            }
            asm volatile("cp.async.wait_group 0;\n");
        }
        __syncthreads();

        const uint32_t sAu = sA0 + (uint32_t)(s * STAGE_H) * 2u;
        const uint32_t sBu = sAu + (uint32_t)A_ST * 2u;

        LOADFRAG(0, 0);
#pragma unroll
        for (int ks = 0; ks < 4; ks++) {
            const int cur = ks & 1;
            if (ks + 1 < 4) LOADFRAG(cur ^ 1, ks + 1);
#pragma unroll
            for (int mi = 0; mi < 4; mi++)
#pragma unroll
                for (int ni = 0; ni < 8; ni++)
                    mma16n8k16(acc[mi][ni], afr[cur][mi], bfr[cur][ni]);
        }
        __syncthreads();
    }
#undef STAGE
#undef LOADFRAG

    // epilogue: two 64-row phases via smem fp32 (64 x 132)
    float* sC = (float*)smh;
    const int gid = lane >> 2;
    for (int p = 0; p < 2; p++) {
        if (wm == p) {
#pragma unroll
            for (int mi = 0; mi < 4; mi++)
#pragma unroll
                for (int ni = 0; ni < 8; ni++) {
                    int rr = mi * 16 + gid;
                    int cc = wn * 64 + ni * 8 + 2 * tig;
                    sC[rr * 132 + cc]           = acc[mi][ni][0];
                    sC[rr * 132 + cc + 1]       = acc[mi][ni][1];
                    sC[(rr + 8) * 132 + cc]     = acc[mi][ni][2];
                    sC[(rr + 8) * 132 + cc + 1] = acc[mi][ni][3];
                }
        }
        __syncthreads();
#pragma unroll
        for (int j = 0; j < 16; j++) {
            int f = tid + j * 128;               // 2048 float4s = 64x128
            int r = f >> 5, c = (f & 31) << 2;
            int lrow = p * 64 + r;
            int gn = n0 + c;
            float4 cv = *(float4*)(sC + r * 132 + c);
            float4 bv = *(const float4*)(biasp + gn);
            if (isGemm1) {
                __half2 h0 = __floats2half2_rn(gelu_exact(cv.x + bv.x),
                                               gelu_exact(cv.y + bv.y));
                __half2 h1 = __floats2half2_rn(gelu_exact(cv.z + bv.z),
                                               gelu_exact(cv.w + bv.w));
                uint2 pk;
                pk.x = *(uint32_t*)&h0;
                pk.y = *(uint32_t*)&h1;
                *(uint2*)(Out + (size_t)(r0 + lrow) * N + gn) = pk;
            } else {
                int pair = stok[lrow];
                if (pair >= 0) {
                    float g = sgate[lrow];
                    __half2 h0 = __floats2half2_rn((cv.x + bv.x) * g,
                                                   (cv.y + bv.y) * g);
                    __half2 h1 = __floats2half2_rn((cv.z + bv.z) * g,
                                                   (cv.w + bv.w) * g);
                    uint2 pk;
                    pk.x = *(uint32_t*)&h0;
                    pk.y = *(uint32_t*)&h1;
                    *(uint2*)(Out + (size_t)pair * N + gn) = pk;
                }
            }
        }
        __syncthreads();
    }
}

// ---------------------------------------------------------------------------
// Kernel 6: combine, uint4-vectorized (8 halves per load, 4 pairs, fp32 acc)
// thread i handles token t = i >> 7, column group c = (i & 127) * 8
// ---------------------------------------------------------------------------
__global__ void combine_kernel(float* __restrict__ y) {
    const int i = blockIdx.x * 256 + threadIdx.x;   // over T * O/8 groups
    const int t = i >> 7;                           // O/8 = 128 groups per token
    const int c = i & 127;
    const uint4* yp = (const uint4*)g_yph;          // 8 halves per uint4
    size_t base = (size_t)t * TOPK * 128 + c;
    float s0 = 0.f, s1 = 0.f, s2 = 0.f, s3 = 0.f, s4 = 0.f, s5 = 0.f, s6 = 0.f, s7 = 0.f;
#pragma unroll
    for (int k = 0; k < TOPK; k++) {
        uint4 pk = yp[base + (size_t)k * 128];
        float2 f0 = __half22float2(*(__half2*)&pk.x);
        float2 f1 = __half22float2(*(__half2*)&pk.y);
        float2 f2 = __half22float2(*(__half2*)&pk.z);
        float2 f3 = __half22float2(*(__half2*)&pk.w);
        s0 += f0.x; s1 += f0.y; s2 += f1.x; s3 += f1.y;
        s4 += f2.x; s5 += f2.y; s6 += f3.x; s7 += f3.y;
    }
    float4* y4 = (float4*)(y + (size_t)t * O_DIM + c * 8);
    y4[0] = make_float4(s0, s1, s2, s3);
    y4[1] = make_float4(s4, s5, s6, s7);
}

// ---------------------------------------------------------------------------
extern "C" void kernel_launch(void* const* d_in, const int* in_sizes, int n_in,
                              void* d_out, int out_size) {
    const float* x     = (const float*)d_in[0];
    const float* gamma = (const float*)d_in[1];
    const float* beta  = (const float*)d_in[2];
    const float* rw    = (const float*)d_in[3];
    const float* rb    = (const float*)d_in[4];
    const float* w1    = (const float*)d_in[5];
    const float* b1    = (const float*)d_in[6];
    const float* w2    = (const float*)d_in[7];
    const float* b2    = (const float*)d_in[8];
    float* y = (float*)d_out;

    __half *xnh_p = nullptr, *hh_p = nullptr, *yph_p = nullptr;
    __half *w1t_p = nullptr, *w2t_p = nullptr;
    int *cnt_p = nullptr, *fill_p = nullptr;
    cudaGetSymbolAddress((void**)&xnh_p, g_xnh);
    cudaGetSymbolAddress((void**)&hh_p, g_hh);
    cudaGetSymbolAddress((void**)&yph_p, g_yph);
    cudaGetSymbolAddress((void**)&w1t_p, g_w1t);
    cudaGetSymbolAddress((void**)&w2t_p, g_w2t);
    cudaGetSymbolAddress((void**)&cnt_p, g_cnt);
    cudaGetSymbolAddress((void**)&fill_p, g_fill);

    cudaFuncSetAttribute(moe_gemm_h,
                         cudaFuncAttributeMaxDynamicSharedMemorySize, GEMM_SMEM);

    cudaMemsetAsync(cnt_p, 0, NE * sizeof(int));
    cudaMemsetAsync(fill_p, 0, NE * sizeof(int));

    dim3 tb(32, 8);
    transpose_h_kernel<<<dim3(H_DIM / 32, D_DIM / 32, NE), tb>>>(w1, w1t_p, D_DIM, H_DIM);
    transpose_h_kernel<<<dim3(O_DIM / 32, H_DIM / 32, NE), tb>>>(w2, w2t_p, H_DIM, O_DIM);

    ln_router_kernel<<<T_TOK / 8, 256>>>(x, gamma, beta, rw, rb);
    offsets_kernel<<<1, 256>>>();
    scatter_kernel<<<T_TOK / 128, 128>>>();

    dim3 g1(H_DIM / 128, MAXTILES);
    dim3 g2(O_DIM / 128, MAXTILES);
    moe_gemm_h<<<g1, 128, GEMM_SMEM>>>(xnh_p, w1t_p, b1, hh_p, D_DIM, H_DIM, 1);
    moe_gemm_h<<<g2, 128, GEMM_SMEM>>>(hh_p, w2t_p, b2, yph_p, H_DIM, O_DIM, 0);

    combine_kernel<<<(T_TOK * O_DIM / 8) / 256, 256>>>(y);
}